// round 1
// baseline (speedup 1.0000x reference)
#include <cuda_runtime.h>
#include <cstdint>

// Problem constants
#define Tn 1024
#define Dn 2048
#define Hn 7168
#define En 8
#define Kn 2
#define Pn (Tn * Kn)              // 2048 (token, k) pairs
#define TILE_M 128
#define MAX_SLOTS (Pn + En * TILE_M)   // 3072 (per-expert padding worst case)
#define MAX_TILES (Pn / TILE_M + En)   // 24

// Scratch (device globals: no allocation allowed in kernel_launch)
__device__ int   g_slot_token[MAX_SLOTS];
__device__ float g_slot_w[MAX_SLOTS];
__device__ int   g_tile_expert[MAX_TILES];
__device__ int   g_tile_base[MAX_TILES];
__device__ __align__(16) float g_hact[(size_t)MAX_SLOTS * Hn];  // ~88 MB

// ---------------------------------------------------------------------------
// Routing: deterministic stable scatter of pairs into per-expert segments,
// each segment padded to a multiple of TILE_M. Builds the tile table.
// ---------------------------------------------------------------------------
__global__ void route_kernel(const int* __restrict__ sel,
                             const float* __restrict__ wts) {
    __shared__ int s_e[Pn];
    __shared__ int s_cnt[En];
    __shared__ int s_base[En];
    int tid = threadIdx.x;

    if (tid < En) s_cnt[tid] = 0;
    __syncthreads();

    for (int i = tid; i < Pn; i += blockDim.x) {
        int e = sel[i];
        s_e[i] = e;
        atomicAdd(&s_cnt[e], 1);
    }
    __syncthreads();

    if (tid == 0) {
        int base = 0;
        int tile = 0;
        for (int e = 0; e < En; e++) {
            s_base[e] = base;
            int padded = ((s_cnt[e] + TILE_M - 1) / TILE_M) * TILE_M;
            for (int m = 0; m < padded; m += TILE_M) {
                g_tile_expert[tile] = e;
                g_tile_base[tile]   = base + m;
                tile++;
            }
            base += padded;
        }
        for (; tile < MAX_TILES; tile++) g_tile_expert[tile] = -1;
    }
    __syncthreads();

    // invalidate all slots first
    for (int s = tid; s < MAX_SLOTS; s += blockDim.x) g_slot_token[s] = -1;
    __syncthreads();

    // stable rank within expert (O(P^2 / nthreads), trivial at P=2048)
    for (int i = tid; i < Pn; i += blockDim.x) {
        int e = s_e[i];
        int rank = 0;
        for (int j = 0; j < i; j++) rank += (s_e[j] == e) ? 1 : 0;
        int slot = s_base[e] + rank;
        g_slot_token[slot] = i / Kn;   // token index
        g_slot_w[slot]     = wts[i];   // routing weight
    }
}

__global__ void zero_kernel(float* __restrict__ out) {
    int i = blockIdx.x * blockDim.x + threadIdx.x;
    out[i] = 0.0f;
}

// ---------------------------------------------------------------------------
// GEMM1 (fused): hact[slot, h] = silu(x.W1^T) * (x.W3^T), per-expert.
// C tile: 128 slots x 64 h. K-loop over D in chunks of 16.
// 256 threads: 16x16 grid, each thread 8 rows x 4 cols, for BOTH matrices.
// ---------------------------------------------------------------------------
__global__ __launch_bounds__(256, 2) void gemm1_kernel(
    const float* __restrict__ x,
    const float* __restrict__ w1,
    const float* __restrict__ w3) {
    int e = g_tile_expert[blockIdx.y];
    if (e < 0) return;
    int base = g_tile_base[blockIdx.y];
    int h0 = blockIdx.x * 64;

    __shared__ __align__(16) float sA[16][TILE_M];   // [kk][m]
    __shared__ __align__(16) float sB1[16][64];      // [kk][n]
    __shared__ __align__(16) float sB3[16][64];
    __shared__ int s_tok[TILE_M];

    int tid = threadIdx.x;
    if (tid < TILE_M) s_tok[tid] = g_slot_token[base + tid];
    __syncthreads();

    const float* w1e = w1 + ((size_t)e * Hn + h0) * Dn;
    const float* w3e = w3 + ((size_t)e * Hn + h0) * Dn;

    float acc1[8][4];
    float acc3[8][4];
#pragma unroll
    for (int r = 0; r < 8; r++)
#pragma unroll
        for (int c = 0; c < 4; c++) { acc1[r][c] = 0.f; acc3[r][c] = 0.f; }

    const int tm = tid >> 4;      // 0..15 -> rows tm*8 .. tm*8+7
    const int tn = tid & 15;      // 0..15 -> cols tn*4 .. tn*4+3
    const int lm = tid >> 1;      // A-load row 0..127
    const int lh = tid & 1;       // A-load half (8 floats each)
    const int bn = tid >> 2;      // B-load row 0..63
    const int bs = tid & 3;       // B-load segment 0..3

    const int tokL = s_tok[lm];
    const float* aL = x + (size_t)(tokL < 0 ? 0 : tokL) * Dn + lh * 8;

    for (int d0 = 0; d0 < Dn; d0 += 16) {
        // ---- load A (gathered x rows), transposed into smem ----
        float4 v0 = make_float4(0.f, 0.f, 0.f, 0.f);
        float4 v1 = v0;
        if (tokL >= 0) {
            v0 = *(const float4*)(aL + d0);
            v1 = *(const float4*)(aL + d0 + 4);
        }
        sA[lh * 8 + 0][lm] = v0.x; sA[lh * 8 + 1][lm] = v0.y;
        sA[lh * 8 + 2][lm] = v0.z; sA[lh * 8 + 3][lm] = v0.w;
        sA[lh * 8 + 4][lm] = v1.x; sA[lh * 8 + 5][lm] = v1.y;
        sA[lh * 8 + 6][lm] = v1.z; sA[lh * 8 + 7][lm] = v1.w;

        // ---- load B1 / B3 tiles, transposed into smem ----
        float4 b1 = *(const float4*)(w1e + (size_t)bn * Dn + d0 + bs * 4);
        float4 b3 = *(const float4*)(w3e + (size_t)bn * Dn + d0 + bs * 4);
        sB1[bs * 4 + 0][bn] = b1.x; sB1[bs * 4 + 1][bn] = b1.y;
        sB1[bs * 4 + 2][bn] = b1.z; sB1[bs * 4 + 3][bn] = b1.w;
        sB3[bs * 4 + 0][bn] = b3.x; sB3[bs * 4 + 1][bn] = b3.y;
        sB3[bs * 4 + 2][bn] = b3.z; sB3[bs * 4 + 3][bn] = b3.w;
        __syncthreads();

#pragma unroll
        for (int kk = 0; kk < 16; kk++) {
            const float4 a0 = *(const float4*)&sA[kk][tm * 8];
            const float4 a1 = *(const float4*)&sA[kk][tm * 8 + 4];
            const float4 p1 = *(const float4*)&sB1[kk][tn * 4];
            const float4 p3 = *(const float4*)&sB3[kk][tn * 4];
            float a[8]  = {a0.x, a0.y, a0.z, a0.w, a1.x, a1.y, a1.z, a1.w};
            float q1[4] = {p1.x, p1.y, p1.z, p1.w};
            float q3[4] = {p3.x, p3.y, p3.z, p3.w};
#pragma unroll
            for (int r = 0; r < 8; r++)
#pragma unroll
                for (int c = 0; c < 4; c++) {
                    acc1[r][c] = fmaf(a[r], q1[c], acc1[r][c]);
                    acc3[r][c] = fmaf(a[r], q3[c], acc3[r][c]);
                }
        }
        __syncthreads();
    }

    // ---- epilogue: silu(gate) * up -> g_hact ----
#pragma unroll
    for (int r = 0; r < 8; r++) {
        int row = base + tm * 8 + r;
        float* dst = &g_hact[(size_t)row * Hn + h0 + tn * 4];
        float4 o;
        {
            float g = acc1[r][0];
            o.x = (g / (1.f + __expf(-g))) * acc3[r][0];
            g = acc1[r][1];
            o.y = (g / (1.f + __expf(-g))) * acc3[r][1];
            g = acc1[r][2];
            o.z = (g / (1.f + __expf(-g))) * acc3[r][2];
            g = acc1[r][3];
            o.w = (g / (1.f + __expf(-g))) * acc3[r][3];
        }
        *(float4*)dst = o;
    }
}

// ---------------------------------------------------------------------------
// GEMM2: out[tok, d] += w_pair * sum_h hact[slot, h] * w2[e, h, d]
// C tile: 128 slots x 64 d. K-loop over H in chunks of 16.
// ---------------------------------------------------------------------------
__global__ __launch_bounds__(256, 2) void gemm2_kernel(
    const float* __restrict__ w2,
    float* __restrict__ out) {
    int e = g_tile_expert[blockIdx.y];
    if (e < 0) return;
    int base = g_tile_base[blockIdx.y];
    int d0 = blockIdx.x * 64;

    __shared__ __align__(16) float sA[16][TILE_M];   // [kk][m]
    __shared__ __align__(16) float sB[16][64];       // [kk][n]
    __shared__ int   s_tok[TILE_M];
    __shared__ float s_w[TILE_M];

    int tid = threadIdx.x;
    if (tid < TILE_M) {
        s_tok[tid] = g_slot_token[base + tid];
        s_w[tid]   = g_slot_w[base + tid];
    }
    __syncthreads();

    const float* w2e = w2 + (size_t)e * Hn * Dn + d0;

    float acc[8][4];
#pragma unroll
    for (int r = 0; r < 8; r++)
#pragma unroll
        for (int c = 0; c < 4; c++) acc[r][c] = 0.f;

    const int tm = tid >> 4;
    const int tn = tid & 15;
    const int lm = tid >> 1;
    const int lh = tid & 1;
    const int bk = tid >> 4;      // B row (kk) 0..15
    const int bs4 = tid & 15;     // B col segment 0..15

    const float* aL = g_hact + (size_t)(base + lm) * Hn + lh * 8;

    for (int h0 = 0; h0 < Hn; h0 += 16) {
        // A: hact rows (always valid memory; invalid rows are zeros)
        float4 v0 = *(const float4*)(aL + h0);
        float4 v1 = *(const float4*)(aL + h0 + 4);
        sA[lh * 8 + 0][lm] = v0.x; sA[lh * 8 + 1][lm] = v0.y;
        sA[lh * 8 + 2][lm] = v0.z; sA[lh * 8 + 3][lm] = v0.w;
        sA[lh * 8 + 4][lm] = v1.x; sA[lh * 8 + 5][lm] = v1.y;
        sA[lh * 8 + 6][lm] = v1.z; sA[lh * 8 + 7][lm] = v1.w;

        // B: w2 rows are contiguous in d -> direct coalesced float4 store
        float4 b = *(const float4*)(w2e + (size_t)(h0 + bk) * Dn + bs4 * 4);
        *(float4*)&sB[bk][bs4 * 4] = b;
        __syncthreads();

#pragma unroll
        for (int kk = 0; kk < 16; kk++) {
            const float4 a0 = *(const float4*)&sA[kk][tm * 8];
            const float4 a1 = *(const float4*)&sA[kk][tm * 8 + 4];
            const float4 p  = *(const float4*)&sB[kk][tn * 4];
            float a[8] = {a0.x, a0.y, a0.z, a0.w, a1.x, a1.y, a1.z, a1.w};
            float q[4] = {p.x, p.y, p.z, p.w};
#pragma unroll
            for (int r = 0; r < 8; r++)
#pragma unroll
                for (int c = 0; c < 4; c++)
                    acc[r][c] = fmaf(a[r], q[c], acc[r][c]);
        }
        __syncthreads();
    }

    // epilogue: weighted atomic accumulate into out (exactly K=2 adds per
    // element, float add is commutative -> deterministic)
#pragma unroll
    for (int r = 0; r < 8; r++) {
        int m = tm * 8 + r;
        int tok = s_tok[m];
        if (tok >= 0) {
            float wgt = s_w[m];
            float* dst = out + (size_t)tok * Dn + d0 + tn * 4;
            atomicAdd(dst + 0, wgt * acc[r][0]);
            atomicAdd(dst + 1, wgt * acc[r][1]);
            atomicAdd(dst + 2, wgt * acc[r][2]);
            atomicAdd(dst + 3, wgt * acc[r][3]);
        }
    }
}

// ---------------------------------------------------------------------------
extern "C" void kernel_launch(void* const* d_in, const int* in_sizes, int n_in,
                              void* d_out, int out_size) {
    const float* x   = (const float*)d_in[0];   // inputs [T, D]
    const float* wts = (const float*)d_in[1];   // weights [T, K]
    const int*   sel = (const int*)d_in[2];     // selected_experts [T, K]
    const float* w1  = (const float*)d_in[3];   // [E, H, D]
    const float* w2  = (const float*)d_in[4];   // [E, H, D]
    const float* w3  = (const float*)d_in[5];   // [E, H, D]
    float* out = (float*)d_out;                 // [T, D]

    route_kernel<<<1, 1024>>>(sel, wts);
    zero_kernel<<<(Tn * Dn) / 256, 256>>>(out);
    gemm1_kernel<<<dim3(Hn / 64, MAX_TILES), 256>>>(x, w1, w3);
    gemm2_kernel<<<dim3(Dn / 64, MAX_TILES), 256>>>(w2, out);
}

// round 3
// speedup vs baseline: 2.0751x; 2.0751x over previous
#include <cuda_runtime.h>
#include <cuda_bf16.h>
#include <cstdint>

// Problem constants
#define Tn 1024
#define Dn 2048
#define Hn 7168
#define En 8
#define Kn 2
#define Pn (Tn * Kn)                   // 2048 (token,k) pairs
#define TILE_M 128
#define MAX_SLOTS (Pn + En * TILE_M)   // 3072
#define MAX_TILES (Pn / TILE_M + En)   // 24

#define G1_KIT (Dn / 32)               // 64 K-chunks of 32
#define G2_KIT (Hn / 32)               // 224 K-chunks of 32

// Scratch (device globals; no allocation allowed)
__device__ int   g_slot_token[MAX_SLOTS];
__device__ float g_slot_w[MAX_SLOTS];
__device__ int   g_tile_expert[MAX_TILES];
__device__ int   g_tile_base[MAX_TILES];
// hact stored pre-split as bf16 hi/lo planes (~44 MB each)
__device__ __align__(16) unsigned short g_hact_hi[(size_t)MAX_SLOTS * Hn];
__device__ __align__(16) unsigned short g_hact_lo[(size_t)MAX_SLOTS * Hn];

// ---------------------------------------------------------------------------
// Helpers
// ---------------------------------------------------------------------------
__device__ __forceinline__ uint32_t smem_u32(const void* p) {
    uint32_t a;
    asm("{ .reg .u64 t; cvta.to.shared.u64 t, %1; cvt.u32.u64 %0, t; }"
        : "=r"(a) : "l"(p));
    return a;
}

// swizzles for 128B-row / 256B-row tiles (base must be 1024B aligned)
__device__ __forceinline__ uint32_t sw128(uint32_t o) {
    return o ^ (((o >> 7) & 7u) << 4);
}
__device__ __forceinline__ uint32_t sw256(uint32_t o) {
    return o ^ (((o >> 8) & 7u) << 4);
}

__device__ __forceinline__ void ldsm4(uint32_t* r, uint32_t a) {
    asm volatile("ldmatrix.sync.aligned.m8n8.x4.shared.b16 {%0,%1,%2,%3}, [%4];"
        : "=r"(r[0]), "=r"(r[1]), "=r"(r[2]), "=r"(r[3]) : "r"(a));
}
__device__ __forceinline__ void ldsm4t(uint32_t* r, uint32_t a) {
    asm volatile("ldmatrix.sync.aligned.m8n8.x4.trans.shared.b16 {%0,%1,%2,%3}, [%4];"
        : "=r"(r[0]), "=r"(r[1]), "=r"(r[2]), "=r"(r[3]) : "r"(a));
}
__device__ __forceinline__ void mma16816(float* c, const uint32_t* a,
                                         uint32_t b0, uint32_t b1) {
    asm volatile(
        "mma.sync.aligned.m16n8k16.row.col.f32.bf16.bf16.f32 "
        "{%0,%1,%2,%3}, {%4,%5,%6,%7}, {%8,%9}, {%0,%1,%2,%3};"
        : "+f"(c[0]), "+f"(c[1]), "+f"(c[2]), "+f"(c[3])
        : "r"(a[0]), "r"(a[1]), "r"(a[2]), "r"(a[3]), "r"(b0), "r"(b1));
}

// bf16 split: hi = truncate(v) (exact in both bf16 and fp32), lo = rn(v - hi)
__device__ __forceinline__ uint32_t pack_hi(float a, float b) {
    return (__float_as_uint(a) >> 16) | (__float_as_uint(b) & 0xffff0000u);
}
__device__ __forceinline__ uint32_t pack_lo(float a, float b) {
    float ha = __uint_as_float(__float_as_uint(a) & 0xffff0000u);
    float hb = __uint_as_float(__float_as_uint(b) & 0xffff0000u);
    unsigned short la = __bfloat16_as_ushort(__float2bfloat16(a - ha));
    unsigned short lb = __bfloat16_as_ushort(__float2bfloat16(b - hb));
    return (uint32_t)la | ((uint32_t)lb << 16);
}

// ---------------------------------------------------------------------------
// Routing
// ---------------------------------------------------------------------------
__global__ void route_kernel(const int* __restrict__ sel,
                             const float* __restrict__ wts) {
    __shared__ int s_e[Pn];
    __shared__ int s_cnt[En];
    __shared__ int s_base[En];
    int tid = threadIdx.x;

    if (tid < En) s_cnt[tid] = 0;
    __syncthreads();
    for (int i = tid; i < Pn; i += blockDim.x) {
        int e = sel[i];
        s_e[i] = e;
        atomicAdd(&s_cnt[e], 1);
    }
    __syncthreads();
    if (tid == 0) {
        int base = 0, tile = 0;
        for (int e = 0; e < En; e++) {
            s_base[e] = base;
            int padded = ((s_cnt[e] + TILE_M - 1) / TILE_M) * TILE_M;
            for (int m = 0; m < padded; m += TILE_M) {
                g_tile_expert[tile] = e;
                g_tile_base[tile]   = base + m;
                tile++;
            }
            base += padded;
        }
        for (; tile < MAX_TILES; tile++) g_tile_expert[tile] = -1;
    }
    __syncthreads();
    for (int s = tid; s < MAX_SLOTS; s += blockDim.x) g_slot_token[s] = -1;
    __syncthreads();
    for (int i = tid; i < Pn; i += blockDim.x) {
        int e = s_e[i];
        int rank = 0;
        for (int j = 0; j < i; j++) rank += (s_e[j] == e) ? 1 : 0;
        int slot = s_base[e] + rank;
        g_slot_token[slot] = i / Kn;
        g_slot_w[slot]     = wts[i];
    }
}

__global__ void zero_kernel(float* __restrict__ out) {
    int i = blockIdx.x * blockDim.x + threadIdx.x;
    out[i] = 0.0f;
}

// ---------------------------------------------------------------------------
// GEMM1: hact[slot, h0+c] = silu(x.W1^T) * (x.W3^T)
// C tile 128x128 (n 0-63 = gate from w1, 64-127 = up from w3), BK=32.
// SMEM plane layout (A and B): row r (m or n) = 128B: [hi 32xbf16 | lo 32xbf16].
// ---------------------------------------------------------------------------
__global__ __launch_bounds__(256) void gemm1_kernel(
    const float* __restrict__ x,
    const float* __restrict__ w1,
    const float* __restrict__ w3) {
    int e = g_tile_expert[blockIdx.x];
    if (e < 0) return;
    int base = g_tile_base[blockIdx.x];
    int h0 = blockIdx.y * 64;

    extern __shared__ char dsm[];
    __shared__ int s_tok[TILE_M];
    uint32_t raw = smem_u32(dsm);
    uint32_t sb = (raw + 1023u) & ~1023u;
    char* sp = dsm + (sb - raw);

    int tid = threadIdx.x;
    if (tid < TILE_M) s_tok[tid] = g_slot_token[base + tid];
    __syncthreads();

    const int warp = tid >> 5, lane = tid & 31;
    const int wm = warp & 3, wn = warp >> 2;   // 4m x 2n, warp tile 32x64

    // global->smem staging: thread t covers row t>>1, k [kseg, kseg+16)
    const int row = tid >> 1, kseg = (tid & 1) * 16;
    const int tok = s_tok[row];
    const float* aP = x + (size_t)(tok < 0 ? 0 : tok) * Dn + kseg;
    const float* bP = (row < 64)
        ? w1 + ((size_t)e * Hn + h0 + row) * Dn + kseg
        : w3 + ((size_t)e * Hn + h0 + row - 64) * Dn + kseg;
    const uint32_t so = (uint32_t)row * 128u + (uint32_t)kseg * 2u;

    // ldmatrix lane offsets
    const uint32_t a_m  = (uint32_t)(lane & 15);
    const uint32_t a_kc = (uint32_t)(lane >> 4);         // +16B
    const uint32_t b_n  = (uint32_t)((lane & 7) | ((lane >> 4) << 3));
    const uint32_t b_kc = (uint32_t)((lane >> 3) & 1);   // +16B

    float C[2][8][4];
#pragma unroll
    for (int i = 0; i < 2; i++)
#pragma unroll
        for (int j = 0; j < 8; j++)
#pragma unroll
            for (int k = 0; k < 4; k++) C[i][j][k] = 0.f;

    float4 ra[4], rb[4];

#define LDG1(c) do {                                                        \
    const float* bq = bP + (size_t)(c) * 32;                                \
    rb[0] = __ldg((const float4*)bq + 0); rb[1] = __ldg((const float4*)bq + 1); \
    rb[2] = __ldg((const float4*)bq + 2); rb[3] = __ldg((const float4*)bq + 3); \
    if (tok >= 0) {                                                         \
        const float* aq = aP + (size_t)(c) * 32;                            \
        ra[0] = __ldg((const float4*)aq + 0); ra[1] = __ldg((const float4*)aq + 1); \
        ra[2] = __ldg((const float4*)aq + 2); ra[3] = __ldg((const float4*)aq + 3); \
    } else {                                                                \
        ra[0] = ra[1] = ra[2] = ra[3] = make_float4(0.f, 0.f, 0.f, 0.f);    \
    }                                                                       \
} while (0)

#define STS1(buf) do {                                                      \
    char* Ab = sp + (buf) * 32768;                                          \
    char* Bb = Ab + 16384;                                                  \
    _Pragma("unroll")                                                       \
    for (int j = 0; j < 4; j++) {                                           \
        uint32_t o = so + j * 8;                                            \
        float4 v = ra[j];                                                   \
        *(uint2*)(Ab + sw128(o)) = make_uint2(pack_hi(v.x, v.y), pack_hi(v.z, v.w)); \
        *(uint2*)(Ab + sw128(o + 64)) = make_uint2(pack_lo(v.x, v.y), pack_lo(v.z, v.w)); \
        v = rb[j];                                                          \
        *(uint2*)(Bb + sw128(o)) = make_uint2(pack_hi(v.x, v.y), pack_hi(v.z, v.w)); \
        *(uint2*)(Bb + sw128(o + 64)) = make_uint2(pack_lo(v.x, v.y), pack_lo(v.z, v.w)); \
    }                                                                       \
} while (0)

#define COMP1(buf) do {                                                     \
    uint32_t Au = sb + (buf) * 32768u;                                      \
    uint32_t Bu = Au + 16384u;                                              \
    _Pragma("unroll")                                                       \
    for (int k16 = 0; k16 < 2; k16++) {                                     \
        uint32_t aH[2][4], aL[2][4];                                        \
        _Pragma("unroll")                                                   \
        for (int mt = 0; mt < 2; mt++) {                                    \
            uint32_t o = (uint32_t)(wm * 32 + mt * 16 + a_m) * 128u + k16 * 32u + a_kc * 16u; \
            ldsm4(aH[mt], Au + sw128(o));                                   \
            ldsm4(aL[mt], Au + sw128(o + 64));                              \
        }                                                                   \
        _Pragma("unroll")                                                   \
        for (int ng = 0; ng < 4; ng++) {                                    \
            uint32_t o = (uint32_t)(wn * 64 + ng * 16 + b_n) * 128u + k16 * 32u + b_kc * 16u; \
            uint32_t bH[4], bL[4];                                          \
            ldsm4(bH, Bu + sw128(o));                                       \
            ldsm4(bL, Bu + sw128(o + 64));                                  \
            _Pragma("unroll")                                               \
            for (int mt = 0; mt < 2; mt++) {                                \
                mma16816(C[mt][2 * ng],     aH[mt], bH[0], bH[1]);          \
                mma16816(C[mt][2 * ng + 1], aH[mt], bH[2], bH[3]);          \
                mma16816(C[mt][2 * ng],     aL[mt], bH[0], bH[1]);          \
                mma16816(C[mt][2 * ng + 1], aL[mt], bH[2], bH[3]);          \
                mma16816(C[mt][2 * ng],     aH[mt], bL[0], bL[1]);          \
                mma16816(C[mt][2 * ng + 1], aH[mt], bL[2], bL[3]);          \
            }                                                               \
        }                                                                   \
    }                                                                       \
} while (0)

    LDG1(0);
    STS1(0);
    for (int c = 0; c < G1_KIT; c++) {
        __syncthreads();
        if (c + 1 < G1_KIT) LDG1(c + 1);
        COMP1(c & 1);
        if (c + 1 < G1_KIT) STS1((c + 1) & 1);
    }
    __syncthreads();

    // C -> smem fp32 [128][132]
    float* sc = (float*)sp;
#pragma unroll
    for (int mt = 0; mt < 2; mt++)
#pragma unroll
        for (int nt = 0; nt < 8; nt++) {
            int r0 = wm * 32 + mt * 16 + (lane >> 2);
            int cc = wn * 64 + nt * 8 + (lane & 3) * 2;
            sc[r0 * 132 + cc]       = C[mt][nt][0];
            sc[r0 * 132 + cc + 1]   = C[mt][nt][1];
            sc[(r0 + 8) * 132 + cc]     = C[mt][nt][2];
            sc[(r0 + 8) * 132 + cc + 1] = C[mt][nt][3];
        }
    __syncthreads();

    // SiLU(gate)*up -> g_hact hi/lo planes
    {
        int m = tid >> 1, coff = (tid & 1) * 32;
        size_t orow = (size_t)(base + m) * Hn + h0 + coff;
#pragma unroll
        for (int j = 0; j < 32; j += 4) {
            float v[4];
#pragma unroll
            for (int jj = 0; jj < 4; jj++) {
                float g = sc[m * 132 + coff + j + jj];
                float u = sc[m * 132 + 64 + coff + j + jj];
                v[jj] = g / (1.f + __expf(-g)) * u;
            }
            *(uint2*)(g_hact_hi + orow + j) =
                make_uint2(pack_hi(v[0], v[1]), pack_hi(v[2], v[3]));
            *(uint2*)(g_hact_lo + orow + j) =
                make_uint2(pack_lo(v[0], v[1]), pack_lo(v[2], v[3]));
        }
    }
#undef LDG1
#undef STS1
#undef COMP1
}

// ---------------------------------------------------------------------------
// GEMM2: out[tok, d0+c] += w * sum_h hact[slot,h] * w2[e,h,d0+c]
// A = hact hi/lo planes ([m][k], 128B rows).  B = w2 in native [k][n] layout,
// stored as separate hi/lo planes of [32][256B], loaded with ldmatrix.trans.
// ---------------------------------------------------------------------------
__global__ __launch_bounds__(256) void gemm2_kernel(
    const float* __restrict__ w2,
    float* __restrict__ out) {
    int e = g_tile_expert[blockIdx.x];
    if (e < 0) return;
    int base = g_tile_base[blockIdx.x];
    int d0 = blockIdx.y * 128;

    extern __shared__ char dsm[];
    __shared__ int   s_tok[TILE_M];
    __shared__ float s_w[TILE_M];
    uint32_t raw = smem_u32(dsm);
    uint32_t sb = (raw + 1023u) & ~1023u;
    char* sp = dsm + (sb - raw);

    int tid = threadIdx.x;
    if (tid < TILE_M) {
        s_tok[tid] = g_slot_token[base + tid];
        s_w[tid]   = g_slot_w[base + tid];
    }
    __syncthreads();

    const int warp = tid >> 5, lane = tid & 31;
    const int wm = warp & 3, wn = warp >> 2;

    // A staging: row t>>1, k [kseg, kseg+16)
    const int row = tid >> 1, kseg = (tid & 1) * 16;
    const unsigned short* hiP = g_hact_hi + (size_t)(base + row) * Hn + kseg;
    const unsigned short* loP = g_hact_lo + (size_t)(base + row) * Hn + kseg;
    const uint32_t soA = (uint32_t)row * 128u + (uint32_t)kseg * 2u;

    // B staging: k-row t>>3 (0..31), d [dseg, dseg+16)
    const int kr = tid >> 3, dseg = (tid & 7) * 16;
    const float* wP = w2 + ((size_t)e * Hn + kr) * Dn + d0 + dseg;
    const uint32_t soB = (uint32_t)kr * 256u + (uint32_t)dseg * 2u;

    // ldmatrix lane offsets
    const uint32_t a_m  = (uint32_t)(lane & 15);
    const uint32_t a_kc = (uint32_t)(lane >> 4);
    const uint32_t t_k  = (uint32_t)((lane & 7) | (((lane >> 3) & 1) << 3));
    const uint32_t t_n8 = (uint32_t)(lane >> 4);         // +16B (8 n)

    float C[2][8][4];
#pragma unroll
    for (int i = 0; i < 2; i++)
#pragma unroll
        for (int j = 0; j < 8; j++)
#pragma unroll
            for (int k = 0; k < 4; k++) C[i][j][k] = 0.f;

    uint4 rh0, rh1, rl0, rl1;
    float4 rb[4];

#define LDG2(c) do {                                                        \
    const unsigned short* hq = hiP + (size_t)(c) * 32;                      \
    const unsigned short* lq = loP + (size_t)(c) * 32;                      \
    rh0 = *(const uint4*)hq; rh1 = *(const uint4*)(hq + 8);                 \
    rl0 = *(const uint4*)lq; rl1 = *(const uint4*)(lq + 8);                 \
    const float* wq = wP + (size_t)(c) * 32 * Dn;                           \
    rb[0] = __ldg((const float4*)wq + 0); rb[1] = __ldg((const float4*)wq + 1); \
    rb[2] = __ldg((const float4*)wq + 2); rb[3] = __ldg((const float4*)wq + 3); \
} while (0)

#define STS2(buf) do {                                                      \
    char* Ab  = sp + (buf) * 32768;                                         \
    char* Bh  = Ab + 16384;                                                 \
    char* Bl  = Ab + 24576;                                                 \
    *(uint4*)(Ab + sw128(soA))       = rh0;                                 \
    *(uint4*)(Ab + sw128(soA + 16))  = rh1;                                 \
    *(uint4*)(Ab + sw128(soA + 64))  = rl0;                                 \
    *(uint4*)(Ab + sw128(soA + 80))  = rl1;                                 \
    _Pragma("unroll")                                                       \
    for (int j = 0; j < 4; j++) {                                           \
        uint32_t o = soB + j * 8;                                           \
        float4 v = rb[j];                                                   \
        *(uint2*)(Bh + sw256(o)) = make_uint2(pack_hi(v.x, v.y), pack_hi(v.z, v.w)); \
        *(uint2*)(Bl + sw256(o)) = make_uint2(pack_lo(v.x, v.y), pack_lo(v.z, v.w)); \
    }                                                                       \
} while (0)

#define COMP2(buf) do {                                                     \
    uint32_t Au  = sb + (buf) * 32768u;                                     \
    uint32_t Bhu = Au + 16384u;                                             \
    uint32_t Blu = Au + 24576u;                                             \
    _Pragma("unroll")                                                       \
    for (int k16 = 0; k16 < 2; k16++) {                                     \
        uint32_t aH[2][4], aL[2][4];                                        \
        _Pragma("unroll")                                                   \
        for (int mt = 0; mt < 2; mt++) {                                    \
            uint32_t o = (uint32_t)(wm * 32 + mt * 16 + a_m) * 128u + k16 * 32u + a_kc * 16u; \
            ldsm4(aH[mt], Au + sw128(o));                                   \
            ldsm4(aL[mt], Au + sw128(o + 64));                              \
        }                                                                   \
        _Pragma("unroll")                                                   \
        for (int ng = 0; ng < 4; ng++) {                                    \
            uint32_t o = (k16 * 16u + t_k) * 256u                           \
                       + (uint32_t)(wn * 64 + ng * 16) * 2u + t_n8 * 16u;   \
            uint32_t bH[4], bL[4];                                          \
            ldsm4t(bH, Bhu + sw256(o));                                     \
            ldsm4t(bL, Blu + sw256(o));                                     \
            _Pragma("unroll")                                               \
            for (int mt = 0; mt < 2; mt++) {                                \
                mma16816(C[mt][2 * ng],     aH[mt], bH[0], bH[1]);          \
                mma16816(C[mt][2 * ng + 1], aH[mt], bH[2], bH[3]);          \
                mma16816(C[mt][2 * ng],     aL[mt], bH[0], bH[1]);          \
                mma16816(C[mt][2 * ng + 1], aL[mt], bH[2], bH[3]);          \
                mma16816(C[mt][2 * ng],     aH[mt], bL[0], bL[1]);          \
                mma16816(C[mt][2 * ng + 1], aH[mt], bL[2], bL[3]);          \
            }                                                               \
        }                                                                   \
    }                                                                       \
} while (0)

    LDG2(0);
    STS2(0);
    for (int c = 0; c < G2_KIT; c++) {
        __syncthreads();
        if (c + 1 < G2_KIT) LDG2(c + 1);
        COMP2(c & 1);
        if (c + 1 < G2_KIT) STS2((c + 1) & 1);
    }
    __syncthreads();

    // C -> smem fp32 [128][132]
    float* sc = (float*)sp;
#pragma unroll
    for (int mt = 0; mt < 2; mt++)
#pragma unroll
        for (int nt = 0; nt < 8; nt++) {
            int r0 = wm * 32 + mt * 16 + (lane >> 2);
            int cc = wn * 64 + nt * 8 + (lane & 3) * 2;
            sc[r0 * 132 + cc]       = C[mt][nt][0];
            sc[r0 * 132 + cc + 1]   = C[mt][nt][1];
            sc[(r0 + 8) * 132 + cc]     = C[mt][nt][2];
            sc[(r0 + 8) * 132 + cc + 1] = C[mt][nt][3];
        }
    __syncthreads();

    // weighted accumulate into out (K=2 commutative adds -> deterministic)
    {
        int m = tid >> 1, coff = (tid & 1) * 64;
        int tok = s_tok[m];
        if (tok >= 0) {
            float wgt = s_w[m];
            float* dst = out + (size_t)tok * Dn + d0 + coff;
#pragma unroll 8
            for (int j = 0; j < 64; j++)
                atomicAdd(dst + j, wgt * sc[m * 132 + coff + j]);
        }
    }
#undef LDG2
#undef STS2
#undef COMP2
}

// ---------------------------------------------------------------------------
extern "C" void kernel_launch(void* const* d_in, const int* in_sizes, int n_in,
                              void* d_out, int out_size) {
    const float* x   = (const float*)d_in[0];
    const float* wts = (const float*)d_in[1];
    const int*   sel = (const int*)d_in[2];
    const float* w1  = (const float*)d_in[3];
    const float* w2  = (const float*)d_in[4];
    const float* w3  = (const float*)d_in[5];
    float* out = (float*)d_out;

    cudaFuncSetAttribute(gemm1_kernel,
                         cudaFuncAttributeMaxDynamicSharedMemorySize, 69632);
    cudaFuncSetAttribute(gemm2_kernel,
                         cudaFuncAttributeMaxDynamicSharedMemorySize, 69632);

    route_kernel<<<1, 1024>>>(sel, wts);
    zero_kernel<<<(Tn * Dn) / 256, 256>>>(out);
    // tile index fastest: all M-tiles of one weight tile run concurrently,
    // so weights stream from DRAM once and reuse via L2.
    gemm1_kernel<<<dim3(MAX_TILES, Hn / 64), 256, 69632>>>(x, w1, w3);
    gemm2_kernel<<<dim3(MAX_TILES, Dn / 128), 256, 69632>>>(w2, out);
}